// round 16
// baseline (speedup 1.0000x reference)
#include <cuda_runtime.h>
#include <cuda_fp16.h>

#define NN 100000
#define EC 6400000
#define ED 400000
#define HH 8
#define FIN 5
#define BN_EPS 1e-5
#define L2_EPS 1e-12f
#define NSLICE 8
#define FULLM 0xffffffffu
#define ECP (EC + 4 * NN)
#define EDP (ED + 4 * NN)
#define GN 391                      // ceil(NN/256); all resident at 3 blocks/SM

// ---------------- scratch ----------------
__device__ __align__(16) int g_csrc[ECP];    // padded CSR src lists (by dst)
__device__ __align__(16) int g_csrd[EDP];
__device__ int   g_cntc[NN];                 // true degrees
__device__ int   g_cntd[NN];
__device__ int   g_curc[NN];
__device__ int   g_curd[NN];
__device__ int   g_rowc[NN];                 // padded, 4-aligned row starts
__device__ int   g_rowd[NN];
__device__ int   g_bsumc[GN + 1];
__device__ int   g_bsumd[GN + 1];
__device__ __align__(16) __half g_zh[(NN + 1) * HH]; // fp16 payload; slot NN = zero sentinel
__device__ __align__(16) float  g_h[NN * HH];        // post-BN features
__device__ double   g_stats[5][NSLICE][16];
__device__ unsigned g_arrive[20];
__device__ int      g_mode;

// layer configuration, passed by value
struct Cfg {
    const int* row; const int* cnt; const int* csr;
    const float* Wr; const float* gam; const float* bet;
    const float* Wl;      // NEXT layer's payload weight (if writeZ)
    float* outp;
    int writeZ;
};
struct AllCfg { Cfg c[5]; };

// ---------------- init (must be separate launch: resets sync counters per replay) --
__global__ void k_init() {
    int i = blockIdx.x * blockDim.x + threadIdx.x;
    if (i < NN) { g_cntc[i] = 0; g_cntd[i] = 0; g_curc[i] = 0; g_curd[i] = 0; }
    if (i < 5 * NSLICE * 16) ((double*)g_stats)[i] = 0.0;
    if (i < 20) g_arrive[i] = 0u;
    if (i < HH) g_zh[NN * HH + i] = __float2half(0.f);   // zero sentinel payload
}

__device__ __forceinline__ void load_edge(const void* ei, int E, int e, int& src, int& dst) {
    if (g_mode) {
        const long long* p = (const long long*)ei;
        src = (int)p[e]; dst = (int)p[E + e];
    } else {
        const int* p = (const int*)ei;
        src = p[e]; dst = p[E + e];
    }
}

// ---------------- helpers ----------------
__device__ __forceinline__ void acc_payload(const uint4& a, float acc[HH]) {
    const __half2* ah = (const __half2*)&a;
#pragma unroll
    for (int k = 0; k < 4; k++) {
        float2 fa = __half22float2(ah[k]);
        acc[2 * k]     += fa.x;
        acc[2 * k + 1] += fa.y;
    }
}

__device__ __forceinline__ void gather_row(int s, int d, const int* __restrict__ csr,
                                           float acc[HH]) {
    int n4 = (d + 3) >> 2;
    const int4* ip = (const int4*)(csr + s);   // 4-aligned by construction
    for (int t = 0; t < n4; t++) {
        int4 id = __ldg(ip + t);
        uint4 a0 = __ldg((const uint4*)&g_zh[id.x * HH]);
        uint4 a1 = __ldg((const uint4*)&g_zh[id.y * HH]);
        uint4 a2 = __ldg((const uint4*)&g_zh[id.z * HH]);
        uint4 a3 = __ldg((const uint4*)&g_zh[id.w * HH]);
        acc_payload(a0, acc);
        acc_payload(a1, acc);
        acc_payload(a2, acc);
        acc_payload(a3, acc);
    }
}

__device__ __forceinline__ void stats_block(const float out[HH], int layer, float* sstat) {
    int tid = threadIdx.x;
#pragma unroll
    for (int h = 0; h < HH; h++) {
        float s = out[h];
        float q = out[h] * out[h];
#pragma unroll
        for (int o = 16; o; o >>= 1) {
            s += __shfl_down_sync(FULLM, s, o);
            q += __shfl_down_sync(FULLM, q, o);
        }
        if ((tid & 31) == 0) {
            atomicAdd(&sstat[h], s);
            atomicAdd(&sstat[8 + h], q);
        }
    }
    __syncthreads();
    if (tid < 16) {
        atomicAdd(&g_stats[layer][blockIdx.x & (NSLICE - 1)][tid], (double)sstat[tid]);
        __threadfence();
    }
}

__device__ __forceinline__ void grid_sync(int id) {
    __syncthreads();
    if (threadIdx.x == 0) {
        atomicAdd(&g_arrive[id], 1u);
        while (*(volatile unsigned*)&g_arrive[id] < gridDim.x) {}
        __threadfence();
    }
    __syncthreads();
}

__device__ __forceinline__ void bn_params(int layer, float* sbn, double* sd) {
    int tid = threadIdx.x;
    if (tid < 16) {
        double s = 0.0;
#pragma unroll
        for (int k = 0; k < NSLICE; k++) s += g_stats[layer][k][tid];
        sd[tid] = s;
    }
    __syncthreads();
    if (tid < 8) {
        double m = sd[tid] / (double)NN;
        double v = sd[8 + tid] / (double)NN - m * m;
        sbn[tid] = (float)m;
        sbn[8 + tid] = (float)rsqrt(v + BN_EPS);
    }
    __syncthreads();
}

__device__ __forceinline__ void norm_relu(float out[HH]) {
    float nrm = 0.f;
#pragma unroll
    for (int h = 0; h < HH; h++) nrm += out[h] * out[h];
    float invn = 1.f / fmaxf(sqrtf(nrm), L2_EPS);
#pragma unroll
    for (int h = 0; h < HH; h++) out[h] = fmaxf(out[h] * invn, 0.f);
}

__device__ __forceinline__ void apply_tail(const float out[HH], int i, const float* sbn,
                                           const float* sg, const float* sb, const float* wl,
                                           float* __restrict__ outp, int writeZ) {
    float hv[HH];
#pragma unroll
    for (int h = 0; h < HH; h++)
        hv[h] = (out[h] - sbn[h]) * sbn[8 + h] * sg[h] + sb[h];
    *(float4*)&outp[i * HH]     = make_float4(hv[0], hv[1], hv[2], hv[3]);
    *(float4*)&outp[i * HH + 4] = make_float4(hv[4], hv[5], hv[6], hv[7]);
    if (writeZ) {
        float z[HH];
#pragma unroll
        for (int h = 0; h < HH; h++) {
            float s = 0.f;
#pragma unroll
            for (int f = 0; f < HH; f++) s += hv[f] * wl[h * HH + f];
            z[h] = s;
        }
        __half2 zo[4];
#pragma unroll
        for (int k = 0; k < 4; k++) zo[k] = __floats2half2_rn(z[2 * k], z[2 * k + 1]);
        *(uint4*)&g_zh[i * HH] = *(uint4*)zo;
    }
}

// 256-element block scan in smem (Hillis-Steele); returns exclusive value; total in sh[255]
__device__ __forceinline__ int block_scan256(int v, int* sh) {
    int tid = threadIdx.x;
    sh[tid] = v; __syncthreads();
#pragma unroll
    for (int o = 1; o < 256; o <<= 1) {
        int t = (tid >= o) ? sh[tid - o] : 0;
        __syncthreads();
        sh[tid] += t;
        __syncthreads();
    }
    return sh[tid] - v;   // exclusive
}

// ---------------- THE super-kernel: build + prologue + 5 layers ----------------
__global__ void __launch_bounds__(256, 3) k_super(
    const float* __restrict__ x, const float* __restrict__ W1l,
    const void* __restrict__ eic, const void* __restrict__ eid, AllCfg cfgs)
{
    __shared__ float w[HH * HH], wl[HH * HH], sstat[16], sg[HH], sb[HH], sbn[16];
    __shared__ double sd[16];
    __shared__ int sA[512], sB[512];
    int tid = threadIdx.x;
    int gid = blockIdx.x * blockDim.x + tid;
    int stride = gridDim.x * blockDim.x;

    // ---- phase 0: dtype detect (block 0, warp 0) ----
    if (blockIdx.x == 0 && tid < 32) {
        int v = ((const int*)eic)[2 * tid + 1];
        unsigned ball = __ballot_sync(FULLM, v == 0);
        if (tid == 0) g_mode = (ball == FULLM) ? 1 : 0;
    }
    grid_sync(0);

    // ---- phase 1: degree count (grid-stride over both edge sets) ----
    for (int e = gid; e < EC; e += stride) {
        int src, dst; load_edge(eic, EC, e, src, dst);
        atomicAdd(&g_cntc[dst], 1);
    }
    for (int e = gid; e < ED; e += stride) {
        int src, dst; load_edge(eid, ED, e, src, dst);
        atomicAdd(&g_cntd[dst], 1);
    }
    grid_sync(1);

    // ---- phase 2: per-block chunk scans of padded counts (chunk b = block b) ----
    {
        int g = blockIdx.x * 256 + tid;
        int vc = (g < NN) ? ((g_cntc[g] + 3) & ~3) : 0;
        int exc = block_scan256(vc, sA);
        if (g < NN) g_rowc[g] = exc;
        if (tid == 255) g_bsumc[blockIdx.x] = exc + vc;
        __syncthreads();
        int vd = (g < NN) ? ((g_cntd[g] + 3) & ~3) : 0;
        int exd = block_scan256(vd, sA);
        if (g < NN) g_rowd[g] = exd;
        if (tid == 255) g_bsumd[blockIdx.x] = exd + vd;
    }
    grid_sync(2);

    // ---- phase 3: scan the GN block sums (block 0 -> C, block 1 -> D) ----
    if (blockIdx.x < 2) {
        int* bs = (blockIdx.x == 0) ? g_bsumc : g_bsumd;
        // load GN=391 values into 512-slot smem (2 per thread)
        int p0 = tid, p1 = tid + 256;
        sA[p0] = (p0 < GN) ? bs[p0] : 0;
        sA[p1] = (p1 < GN) ? bs[p1] : 0;
        __syncthreads();
        int orig0 = sA[p0], orig1 = sA[p1];
        int* cur = sA; int* nxt = sB;
#pragma unroll
        for (int o = 1; o < 512; o <<= 1) {
            nxt[p0] = cur[p0] + ((p0 >= o) ? cur[p0 - o] : 0);
            nxt[p1] = cur[p1] + ((p1 >= o) ? cur[p1 - o] : 0);
            __syncthreads();
            int* t = cur; cur = nxt; nxt = t;
        }
        if (p0 < GN) bs[p0] = cur[p0] - orig0;   // exclusive
        if (p1 < GN) bs[p1] = cur[p1] - orig1;
    }
    grid_sync(3);

    // ---- phase 4: add block offsets to rows ----
    {
        int g = blockIdx.x * 256 + tid;
        if (g < NN) {
            g_rowc[g] += g_bsumc[blockIdx.x];
            g_rowd[g] += g_bsumd[blockIdx.x];
        }
    }
    grid_sync(4);

    // ---- phase 5: CSR placement (grid-stride, cursor atomics) ----
    for (int e = gid; e < EC; e += stride) {
        int src, dst; load_edge(eic, EC, e, src, dst);
        g_csrc[g_rowc[dst] + atomicAdd(&g_curc[dst], 1)] = src;
    }
    for (int e = gid; e < ED; e += stride) {
        int src, dst; load_edge(eid, ED, e, src, dst);
        g_csrd[g_rowd[dst] + atomicAdd(&g_curd[dst], 1)] = src;
    }
    grid_sync(5);

    // ---- phase 6: pad fill + z_first prologue ----
    if (tid < HH * FIN) w[tid] = W1l[tid];
    __syncthreads();
    for (int i = gid; i < NN; i += stride) {
        int d = g_cntc[i], s = g_rowc[i];
        int pad = (d + 3) & ~3;
        for (int j = d; j < pad; j++) g_csrc[s + j] = NN;
        d = g_cntd[i]; s = g_rowd[i];
        pad = (d + 3) & ~3;
        for (int j = d; j < pad; j++) g_csrd[s + j] = NN;
        float xv[FIN];
#pragma unroll
        for (int f = 0; f < FIN; f++) xv[f] = x[i * FIN + f];
        float z[HH];
#pragma unroll
        for (int h = 0; h < HH; h++) {
            float sum = 0.f;
#pragma unroll
            for (int f = 0; f < FIN; f++) sum += xv[f] * w[h * FIN + f];
            z[h] = sum;
        }
        __half2 zo[4];
#pragma unroll
        for (int k = 0; k < 4; k++) zo[k] = __floats2half2_rn(z[2 * k], z[2 * k + 1]);
        *(uint4*)&g_zh[i * HH] = *(uint4*)zo;
    }
    grid_sync(6);

    // ---- phase 7: the 5 fused layers (R15-proven loop) ----
    int i = gid;
    bool act = i < NN;
    for (int L = 0; L < 5; L++) {
        Cfg cfg = cfgs.c[L];
        int fdim = (L == 0) ? FIN : HH;
        if (tid < HH * fdim) w[tid] = cfg.Wr[tid];
        if (cfg.writeZ && tid < HH * HH) wl[tid] = cfg.Wl[tid];
        if (tid < 16) sstat[tid] = 0.f;
        if (tid < HH) { sg[tid] = cfg.gam[tid]; sb[tid] = cfg.bet[tid]; }
        __syncthreads();

        float out[HH];
#pragma unroll
        for (int h = 0; h < HH; h++) out[h] = 0.f;
        if (act) {
            int s = cfg.row[i], d = cfg.cnt[i];
            float acc[HH];
#pragma unroll
            for (int h = 0; h < HH; h++) acc[h] = 0.f;
            gather_row(s, d, cfg.csr, acc);
            float inv = 1.f / fmaxf((float)d, 1.f);
            if (L == 0) {
                float xv[FIN];
#pragma unroll
                for (int f = 0; f < FIN; f++) xv[f] = x[i * FIN + f];
#pragma unroll
                for (int h = 0; h < HH; h++) {
                    float sum = acc[h] * inv;
#pragma unroll
                    for (int f = 0; f < FIN; f++) sum += xv[f] * w[h * FIN + f];
                    out[h] = sum;
                }
            } else {
                float4 h0 = *(const float4*)&g_h[i * HH];
                float4 h1 = *(const float4*)&g_h[i * HH + 4];
                float hv[HH] = {h0.x, h0.y, h0.z, h0.w, h1.x, h1.y, h1.z, h1.w};
#pragma unroll
                for (int h = 0; h < HH; h++) {
                    float sum = acc[h] * inv;
#pragma unroll
                    for (int f = 0; f < HH; f++) sum += hv[f] * w[h * HH + f];
                    out[h] = sum;
                }
            }
            norm_relu(out);
        }
        stats_block(out, L, sstat);
        grid_sync(7 + 2 * L);
        bn_params(L, sbn, sd);
        if (act) apply_tail(out, i, sbn, sg, sb, wl, cfg.outp, cfg.writeZ);
        if (L < 4) grid_sync(8 + 2 * L);
    }
}

// ---------------- host ----------------
extern "C" void kernel_launch(void* const* d_in, const int* in_sizes, int n_in,
                              void* d_out, int out_size) {
    const float* x   = (const float*)d_in[0];
    const void*  eic = d_in[1];
    const void*  eid = d_in[2];
    const float* W1l = (const float*)d_in[3];
    const float* W1r = (const float*)d_in[4];
    const float* W2l = (const float*)d_in[5];
    const float* W2r = (const float*)d_in[6];
    const float* W3l = (const float*)d_in[7];
    const float* W3r = (const float*)d_in[8];
    const float* W4l = (const float*)d_in[9];
    const float* W4r = (const float*)d_in[10];
    const float* g1 = (const float*)d_in[11]; const float* b1 = (const float*)d_in[12];
    const float* g2 = (const float*)d_in[13]; const float* b2 = (const float*)d_in[14];
    const float* g3 = (const float*)d_in[15]; const float* b3 = (const float*)d_in[16];
    const float* g4 = (const float*)d_in[17]; const float* b4 = (const float*)d_in[18];
    float* out = (float*)d_out;

    const int T = 256;

    int* prc;   cudaGetSymbolAddress((void**)&prc, g_rowc);
    int* prd;   cudaGetSymbolAddress((void**)&prd, g_rowd);
    int* pcc;   cudaGetSymbolAddress((void**)&pcc, g_cntc);
    int* pcd;   cudaGetSymbolAddress((void**)&pcd, g_cntd);
    int* pcsrc; cudaGetSymbolAddress((void**)&pcsrc, g_csrc);
    int* pcsrd; cudaGetSymbolAddress((void**)&pcsrd, g_csrd);
    float* ph;  cudaGetSymbolAddress((void**)&ph, g_h);

    AllCfg cf;
    // layer 1: conv1 + bn1 (next payload W4l)
    cf.c[0] = { prc, pcc, pcsrc, W1r, g1, b1, W4l, ph, 1 };
    // layer 2: conv4 + bn2 (next W2l)
    cf.c[1] = { prc, pcc, pcsrc, W4r, g2, b2, W2l, ph, 1 };
    // layer 3 (ED): conv2 + bn3 (next W3l)
    cf.c[2] = { prd, pcd, pcsrd, W2r, g3, b3, W3l, ph, 1 };
    // layer 4: conv3 + bn4 (next W3l)
    cf.c[3] = { prc, pcc, pcsrc, W3r, g4, b4, W3l, ph, 1 };
    // layer 5: conv3 + bn4 -> d_out
    cf.c[4] = { prc, pcc, pcsrc, W3r, g4, b4, nullptr, out, 0 };

    k_init<<<GN, T>>>();
    k_super<<<GN, T>>>(x, W1l, eic, eid, cf);
}

// round 17
// speedup vs baseline: 1.1101x; 1.1101x over previous
#include <cuda_runtime.h>
#include <cuda_fp16.h>

#define NN 100000
#define EC 6400000
#define ED 400000
#define HH 8
#define FIN 5
#define BN_EPS 1e-5
#define L2_EPS 1e-12f
#define SB 512
#define NBN 196                     // ceil(NN/SB)
#define NSLICE 8
#define FULLM 0xffffffffu
#define ECP (EC + 4 * NN)
#define EDP (ED + 4 * NN)

// ---------------- scratch ----------------
__device__ __align__(16) int g_csrc[ECP];    // padded CSR src lists (by dst)
__device__ __align__(16) int g_csrd[EDP];
__device__ int   g_cntc[NN];                 // true degrees
__device__ int   g_cntd[NN];
__device__ int   g_curc[NN];
__device__ int   g_curd[NN];
__device__ int   g_rowc[NN];                 // padded, 4-aligned row starts
__device__ int   g_rowd[NN];
__device__ int   g_bsumc[256];
__device__ int   g_bsumd[256];
__device__ __align__(16) __half g_zh[(NN + 1) * HH]; // fp16 payload; slot NN = zero sentinel
__device__ __align__(16) float  g_h[NN * HH];        // post-BN features
__device__ double   g_stats[5][NSLICE][16];
__device__ unsigned g_arrive[20];
__device__ int      g_mode;

// layer configuration, passed by value
struct Cfg {
    const int* row; const int* cnt; const int* csr;
    const float* Wr; const float* gam; const float* bet;
    const float* Wl;      // NEXT layer's payload weight (if writeZ)
    float* outp;
    int writeZ;
};
struct AllCfg { Cfg c[5]; };

// ---------------- init + dtype detect (block 0) ----------------
__global__ void k_init(const int* __restrict__ eic32) {
    int i = blockIdx.x * blockDim.x + threadIdx.x;
    if (i < NN) { g_cntc[i] = 0; g_cntd[i] = 0; g_curc[i] = 0; g_curd[i] = 0; }
    if (i < 5 * NSLICE * 16) ((double*)g_stats)[i] = 0.0;
    if (i < 20) g_arrive[i] = 0u;
    if (i < HH) g_zh[NN * HH + i] = __float2half(0.f);   // zero sentinel payload
    if (blockIdx.x == 0 && threadIdx.x < 32) {
        int v = eic32[2 * threadIdx.x + 1];
        unsigned ball = __ballot_sync(FULLM, v == 0);
        if (threadIdx.x == 0) g_mode = (ball == FULLM) ? 1 : 0;
    }
}

__device__ __forceinline__ void load_edge(const void* ei, int E, int e, int& src, int& dst) {
    if (g_mode) {
        const long long* p = (const long long*)ei;
        src = (int)p[e]; dst = (int)p[E + e];
    } else {
        const int* p = (const int*)ei;
        src = p[e]; dst = p[E + e];
    }
}

// ---------------- software grid sync ----------------
__device__ __forceinline__ void grid_sync(int id) {
    __syncthreads();
    if (threadIdx.x == 0) {
        atomicAdd(&g_arrive[id], 1u);
        while (*(volatile unsigned*)&g_arrive[id] < gridDim.x) {}
        __threadfence();
    }
    __syncthreads();
}

// ---------------- fused count over both edge sets (wide grid) ----------------
__global__ void k_count(const void* __restrict__ eic, const void* __restrict__ eid, int gEC) {
    long long b = blockIdx.x;
    if (b < gEC) {
        int e = (int)(b * blockDim.x + threadIdx.x);
        if (e < EC) {
            int src, dst; load_edge(eic, EC, e, src, dst);
            atomicAdd(&g_cntc[dst], 1);
        }
    } else {
        int e = (int)((b - gEC) * blockDim.x + threadIdx.x);
        if (e < ED) {
            int src, dst; load_edge(eid, ED, e, src, dst);
            atomicAdd(&g_cntd[dst], 1);
        }
    }
}

// ---------------- ONE fused scan kernel (3 phases, 2 internal grid syncs) --------
__global__ void __launch_bounds__(512, 3) k_scanf() {
    __shared__ int sh[SB];
    int half = gridDim.x >> 1;                 // = NBN
    bool isC = blockIdx.x < half;
    int b = isC ? blockIdx.x : blockIdx.x - half;
    int tid = threadIdx.x;

    // phase A: per-chunk scan of padded counts
    {
        const int* cnt = isC ? g_cntc : g_cntd;
        int* rowp = isC ? g_rowc : g_rowd;
        int* bsum = isC ? g_bsumc : g_bsumd;
        int g = b * SB + tid;
        int v = (g < NN) ? ((cnt[g] + 3) & ~3) : 0;
        sh[tid] = v; __syncthreads();
#pragma unroll
        for (int o = 1; o < SB; o <<= 1) {
            int t = (tid >= o) ? sh[tid - o] : 0;
            __syncthreads();
            sh[tid] += t;
            __syncthreads();
        }
        if (g < NN) rowp[g] = sh[tid] - v;
        if (tid == SB - 1) bsum[b] = sh[SB - 1];
    }
    grid_sync(10);

    // phase B: blocks 0/1 scan the NBN block sums
    if (blockIdx.x < 2) {
        int* bs = (blockIdx.x == 0) ? g_bsumc : g_bsumd;
        int v = (tid < NBN) ? bs[tid] : 0;
        sh[tid] = v; __syncthreads();
#pragma unroll
        for (int o = 1; o < SB; o <<= 1) {
            int t = (tid >= o) ? sh[tid - o] : 0;
            __syncthreads();
            sh[tid] += t;
            __syncthreads();
        }
        if (tid < NBN) bs[tid] = sh[tid] - v;   // exclusive
    }
    grid_sync(11);

    // phase C: add block offsets
    {
        int* rowp = isC ? g_rowc : g_rowd;
        const int* bsum = isC ? g_bsumc : g_bsumd;
        int g = b * SB + tid;
        if (g < NN) rowp[g] += bsum[b];
    }
}

// ---------------- fused CSR placement (wide grid, cursor-based) ----------------
__global__ void k_place(const void* __restrict__ eic, const void* __restrict__ eid, int gEC) {
    long long b = blockIdx.x;
    if (b < gEC) {
        int e = (int)(b * blockDim.x + threadIdx.x);
        if (e < EC) {
            int src, dst; load_edge(eic, EC, e, src, dst);
            g_csrc[g_rowc[dst] + atomicAdd(&g_curc[dst], 1)] = src;
        }
    } else {
        int e = (int)((b - gEC) * blockDim.x + threadIdx.x);
        if (e < ED) {
            int src, dst; load_edge(eid, ED, e, src, dst);
            g_csrd[g_rowd[dst] + atomicAdd(&g_curd[dst], 1)] = src;
        }
    }
}

// ---------------- gather helpers ----------------
__device__ __forceinline__ void acc_payload(const uint4& a, float acc[HH]) {
    const __half2* ah = (const __half2*)&a;
#pragma unroll
    for (int k = 0; k < 4; k++) {
        float2 fa = __half22float2(ah[k]);
        acc[2 * k]     += fa.x;
        acc[2 * k + 1] += fa.y;
    }
}

__device__ __forceinline__ void gather_row(int s, int d, const int* __restrict__ csr,
                                           float acc[HH]) {
    int n4 = (d + 3) >> 2;
    const int4* ip = (const int4*)(csr + s);   // 4-aligned by construction
    for (int t = 0; t < n4; t++) {
        int4 id = __ldg(ip + t);
        uint4 a0 = __ldg((const uint4*)&g_zh[id.x * HH]);
        uint4 a1 = __ldg((const uint4*)&g_zh[id.y * HH]);
        uint4 a2 = __ldg((const uint4*)&g_zh[id.z * HH]);
        uint4 a3 = __ldg((const uint4*)&g_zh[id.w * HH]);
        acc_payload(a0, acc);
        acc_payload(a1, acc);
        acc_payload(a2, acc);
        acc_payload(a3, acc);
    }
}

// ---------------- block stats -> sliced global doubles ----------------
__device__ __forceinline__ void stats_block(const float out[HH], int layer, float* sstat) {
    int tid = threadIdx.x;
#pragma unroll
    for (int h = 0; h < HH; h++) {
        float s = out[h];
        float q = out[h] * out[h];
#pragma unroll
        for (int o = 16; o; o >>= 1) {
            s += __shfl_down_sync(FULLM, s, o);
            q += __shfl_down_sync(FULLM, q, o);
        }
        if ((tid & 31) == 0) {
            atomicAdd(&sstat[h], s);
            atomicAdd(&sstat[8 + h], q);
        }
    }
    __syncthreads();
    if (tid < 16) {
        atomicAdd(&g_stats[layer][blockIdx.x & (NSLICE - 1)][tid], (double)sstat[tid]);
        __threadfence();
    }
}

__device__ __forceinline__ void bn_params(int layer, float* sbn, double* sd) {
    int tid = threadIdx.x;
    if (tid < 16) {
        double s = 0.0;
#pragma unroll
        for (int k = 0; k < NSLICE; k++) s += g_stats[layer][k][tid];
        sd[tid] = s;
    }
    __syncthreads();
    if (tid < 8) {
        double m = sd[tid] / (double)NN;
        double v = sd[8 + tid] / (double)NN - m * m;
        sbn[tid] = (float)m;
        sbn[8 + tid] = (float)rsqrt(v + BN_EPS);
    }
    __syncthreads();
}

__device__ __forceinline__ void norm_relu(float out[HH]) {
    float nrm = 0.f;
#pragma unroll
    for (int h = 0; h < HH; h++) nrm += out[h] * out[h];
    float invn = 1.f / fmaxf(sqrtf(nrm), L2_EPS);
#pragma unroll
    for (int h = 0; h < HH; h++) out[h] = fmaxf(out[h] * invn, 0.f);
}

__device__ __forceinline__ void apply_tail(const float out[HH], int i, const float* sbn,
                                           const float* sg, const float* sb, const float* wl,
                                           float* __restrict__ outp, int writeZ) {
    float hv[HH];
#pragma unroll
    for (int h = 0; h < HH; h++)
        hv[h] = (out[h] - sbn[h]) * sbn[8 + h] * sg[h] + sb[h];
    *(float4*)&outp[i * HH]     = make_float4(hv[0], hv[1], hv[2], hv[3]);
    *(float4*)&outp[i * HH + 4] = make_float4(hv[4], hv[5], hv[6], hv[7]);
    if (writeZ) {
        float z[HH];
#pragma unroll
        for (int h = 0; h < HH; h++) {
            float s = 0.f;
#pragma unroll
            for (int f = 0; f < HH; f++) s += hv[f] * wl[h * HH + f];
            z[h] = s;
        }
        __half2 zo[4];
#pragma unroll
        for (int k = 0; k < 4; k++) zo[k] = __floats2half2_rn(z[2 * k], z[2 * k + 1]);
        *(uint4*)&g_zh[i * HH] = *(uint4*)zo;
    }
}

// ---------------- persistent mega-kernel: prologue + 5 fused layers (R15-proven) --
__global__ void __launch_bounds__(256, 3) k_mega(
    const float* __restrict__ x, const float* __restrict__ W1l, AllCfg cfgs)
{
    __shared__ float w[HH * HH], wl[HH * HH], sstat[16], sg[HH], sb[HH], sbn[16];
    __shared__ double sd[16];
    int tid = threadIdx.x;
    int gid = blockIdx.x * blockDim.x + tid;
    int stride = gridDim.x * blockDim.x;

    // ---- prologue: CSR pad fill + z = x @ W1l^T ----
    if (tid < HH * FIN) w[tid] = W1l[tid];
    __syncthreads();
    for (int i = gid; i < NN; i += stride) {
        int d = g_cntc[i], s = g_rowc[i];
        int pad = (d + 3) & ~3;
        for (int j = d; j < pad; j++) g_csrc[s + j] = NN;
        d = g_cntd[i]; s = g_rowd[i];
        pad = (d + 3) & ~3;
        for (int j = d; j < pad; j++) g_csrd[s + j] = NN;
        float xv[FIN];
#pragma unroll
        for (int f = 0; f < FIN; f++) xv[f] = x[i * FIN + f];
        float z[HH];
#pragma unroll
        for (int h = 0; h < HH; h++) {
            float sum = 0.f;
#pragma unroll
            for (int f = 0; f < FIN; f++) sum += xv[f] * w[h * FIN + f];
            z[h] = sum;
        }
        __half2 zo[4];
#pragma unroll
        for (int k = 0; k < 4; k++) zo[k] = __floats2half2_rn(z[2 * k], z[2 * k + 1]);
        *(uint4*)&g_zh[i * HH] = *(uint4*)zo;
    }
    grid_sync(0);

    // ---- layer loop ----
    int i = gid;
    bool act = i < NN;
    for (int L = 0; L < 5; L++) {
        Cfg cfg = cfgs.c[L];
        int fdim = (L == 0) ? FIN : HH;
        if (tid < HH * fdim) w[tid] = cfg.Wr[tid];
        if (cfg.writeZ && tid < HH * HH) wl[tid] = cfg.Wl[tid];
        if (tid < 16) sstat[tid] = 0.f;
        if (tid < HH) { sg[tid] = cfg.gam[tid]; sb[tid] = cfg.bet[tid]; }
        __syncthreads();

        float out[HH];
#pragma unroll
        for (int h = 0; h < HH; h++) out[h] = 0.f;
        if (act) {
            int s = cfg.row[i], d = cfg.cnt[i];
            float acc[HH];
#pragma unroll
            for (int h = 0; h < HH; h++) acc[h] = 0.f;
            gather_row(s, d, cfg.csr, acc);
            float inv = 1.f / fmaxf((float)d, 1.f);
            if (L == 0) {
                float xv[FIN];
#pragma unroll
                for (int f = 0; f < FIN; f++) xv[f] = x[i * FIN + f];
#pragma unroll
                for (int h = 0; h < HH; h++) {
                    float sum = acc[h] * inv;
#pragma unroll
                    for (int f = 0; f < FIN; f++) sum += xv[f] * w[h * FIN + f];
                    out[h] = sum;
                }
            } else {
                float4 h0 = *(const float4*)&g_h[i * HH];
                float4 h1 = *(const float4*)&g_h[i * HH + 4];
                float hv[HH] = {h0.x, h0.y, h0.z, h0.w, h1.x, h1.y, h1.z, h1.w};
#pragma unroll
                for (int h = 0; h < HH; h++) {
                    float sum = acc[h] * inv;
#pragma unroll
                    for (int f = 0; f < HH; f++) sum += hv[f] * w[h * HH + f];
                    out[h] = sum;
                }
            }
            norm_relu(out);
        }
        stats_block(out, L, sstat);
        grid_sync(1 + 2 * L);
        bn_params(L, sbn, sd);
        if (act) apply_tail(out, i, sbn, sg, sb, wl, cfg.outp, cfg.writeZ);
        if (L < 4) grid_sync(2 + 2 * L);   // next layer's gather reads g_zh/g_h
    }
}

// ---------------- host ----------------
extern "C" void kernel_launch(void* const* d_in, const int* in_sizes, int n_in,
                              void* d_out, int out_size) {
    const float* x   = (const float*)d_in[0];
    const void*  eic = d_in[1];
    const void*  eid = d_in[2];
    const float* W1l = (const float*)d_in[3];
    const float* W1r = (const float*)d_in[4];
    const float* W2l = (const float*)d_in[5];
    const float* W2r = (const float*)d_in[6];
    const float* W3l = (const float*)d_in[7];
    const float* W3r = (const float*)d_in[8];
    const float* W4l = (const float*)d_in[9];
    const float* W4r = (const float*)d_in[10];
    const float* g1 = (const float*)d_in[11]; const float* b1 = (const float*)d_in[12];
    const float* g2 = (const float*)d_in[13]; const float* b2 = (const float*)d_in[14];
    const float* g3 = (const float*)d_in[15]; const float* b3 = (const float*)d_in[16];
    const float* g4 = (const float*)d_in[17]; const float* b4 = (const float*)d_in[18];
    float* out = (float*)d_out;

    const int T = 256;
    const int gN  = (NN + T - 1) / T;          // 391 blocks; 3/SM residency forced
    const int gEC = (EC + T - 1) / T;
    const int gED = (ED + T - 1) / T;

    int* prc;   cudaGetSymbolAddress((void**)&prc, g_rowc);
    int* prd;   cudaGetSymbolAddress((void**)&prd, g_rowd);
    int* pcc;   cudaGetSymbolAddress((void**)&pcc, g_cntc);
    int* pcd;   cudaGetSymbolAddress((void**)&pcd, g_cntd);
    int* pcsrc; cudaGetSymbolAddress((void**)&pcsrc, g_csrc);
    int* pcsrd; cudaGetSymbolAddress((void**)&pcsrd, g_csrd);
    float* ph;  cudaGetSymbolAddress((void**)&ph, g_h);

    AllCfg cf;
    // layer 1: conv1 + bn1 (next payload W4l)
    cf.c[0] = { prc, pcc, pcsrc, W1r, g1, b1, W4l, ph, 1 };
    // layer 2: conv4 + bn2 (next W2l)
    cf.c[1] = { prc, pcc, pcsrc, W4r, g2, b2, W2l, ph, 1 };
    // layer 3 (ED): conv2 + bn3 (next W3l)
    cf.c[2] = { prd, pcd, pcsrd, W2r, g3, b3, W3l, ph, 1 };
    // layer 4: conv3 + bn4 (next W3l)
    cf.c[3] = { prc, pcc, pcsrc, W3r, g4, b4, W3l, ph, 1 };
    // layer 5: conv3 + bn4 -> d_out
    cf.c[4] = { prc, pcc, pcsrc, W3r, g4, b4, nullptr, out, 0 };

    // ---- 5 launches total ----
    k_init<<<gN, T>>>((const int*)eic);        // + dtype detect
    k_count<<<gEC + gED, T>>>(eic, eid, gEC);
    k_scanf<<<2 * NBN, SB>>>();                // fused scan1+scan2+scan3
    k_place<<<gEC + gED, T>>>(eic, eid, gEC);
    k_mega<<<gN, T>>>(x, W1l, cf);
}